// round 13
// baseline (speedup 1.0000x reference)
#include <cuda_runtime.h>
#include <cuda_bf16.h>
#include <cstdint>

// Problem constants
#define NN   128      // sequence length
#define BB   8        // batch
#define EE   256      // embed dim
#define HH   256      // hidden dim (seq GRU)
#define SS   256      // segment dim
#define TSEG 32       // segment window length
#define G3   768      // 3*H == 3*S (gate dim)
#define TWOH 512      // 2*H == 2*S
#define TRI_CNT  8256                  // N*(N+1)/2
#define OUT_TRI  33816576              // TRI_CNT*B*2S
#define OUT_TOTAL 33820672             // + B*2S (hidden)

typedef unsigned long long ull;

// ------------------------------- scratch -----------------------------------
__device__ float g_x[NN*BB*EE];          // embedded inputs (N*B, E)
__device__ float g_gi_f[NN*BB*G3];       // forward  seq input gates
__device__ float g_gi_r[NN*BB*G3];       // backward seq input gates (step-indexed)
__device__ float g_seqout[NN*BB*TWOH];   // bidirectional GRU outputs (N,B,2H)
__device__ float g_G[NN*BB*G3];          // segment input gates per column j
__device__ float g_h[2*2*BB*HH];         // [parity][dir][b][h] double-buffered seq state
__device__ ull   g_WT2[(SS/2)*G3];       // transposed+paired seg weights:
                                         //   WT2[k2][gate*256+c] = (w[2k2][c], w[2k2+1][c])
__device__ unsigned int g_ctrs[16*32];   // per-(dir,b) barrier counters, 128B apart

__device__ __forceinline__ float sigmf(float x)    { return 1.f/(1.f+__expf(-x)); }
__device__ __forceinline__ float tanhfast(float x) { return 2.f/(1.f+__expf(-2.f*x)) - 1.f; }

// packed fp32x2 FMA (Blackwell FFMA2): d = a*b + d, per 32-bit lane
__device__ __forceinline__ void ffma2(ull &d, ull a, ull b){
    asm("fma.rn.f32x2 %0, %1, %2, %0;" : "+l"(d) : "l"(a), "l"(b));
}
__device__ __forceinline__ float hsum2(ull v){
    float lo, hi;
    asm("mov.b64 {%0,%1}, %2;" : "=f"(lo), "=f"(hi) : "l"(v));
    return lo + hi;
}
__device__ __forceinline__ ull pack2(float lo, float hi){
    ull d;
    asm("mov.b64 %0, {%1,%2};" : "=l"(d) : "f"(lo), "f"(hi));
    return d;
}

// release arrive / acquire poll for the group barriers (no full membar)
__device__ __forceinline__ void bar_arrive(unsigned int* ctr){
    asm volatile("red.release.gpu.global.add.u32 [%0], 1;" :: "l"(ctr) : "memory");
}
__device__ __forceinline__ unsigned int ld_acq(const unsigned int* p){
    unsigned int v;
    asm volatile("ld.acquire.gpu.global.u32 %0, [%1];" : "=r"(v) : "l"(p) : "memory");
    return v;
}

// ----------------------- init (zero) + embedding ----------------------------
__global__ void k_init_embed(float* __restrict__ out,
                             const int* __restrict__ tokens,
                             const float* __restrict__ emb)
{
    long tid    = (long)blockIdx.x*blockDim.x + threadIdx.x;
    long stride = (long)gridDim.x*blockDim.x;
    float4 z = make_float4(0.f,0.f,0.f,0.f);
    float4* o4 = (float4*)out;
    for (long i=tid; i < OUT_TOTAL/4; i+=stride) o4[i] = z;
    if (tid < 2*2*BB*HH) g_h[tid] = 0.f;
    if (tid < 16*32)     g_ctrs[tid] = 0u;
    // embedding: blocks 0..1023 each copy one (n,b) row of 256 floats
    if (blockIdx.x < NN*BB){
        int m = blockIdx.x;
        int tok = tokens[m];
        g_x[(long)m*EE + threadIdx.x] = __ldg(emb + (long)tok*EE + threadIdx.x);
    }
}

// --------------------- transpose + pair segment weights ---------------------
// Whs[row][k] (768 x 256) -> g_WT2[k2][row] with k-pairs packed in one 8B word.
__global__ __launch_bounds__(256) void k_transpose(const float* __restrict__ Whs)
{
    __shared__ float tile[32][33];
    int tk = blockIdx.x*32;          // k-block   (0..224), 32 k = 16 k2
    int tr = blockIdx.y*32;          // row-block (0..736)
    int tx = threadIdx.x & 31, ty = threadIdx.x >> 5;   // 32 x 8
    #pragma unroll
    for (int r=ty; r<32; r+=8)
        tile[r][tx] = __ldg(Whs + (long)(tr+r)*SS + tk + tx);
    __syncthreads();
    #pragma unroll
    for (int k2=ty; k2<16; k2+=8){
        ull v = pack2(tile[tx][2*k2], tile[tx][2*k2+1]);
        g_WT2[(long)((tk>>1)+k2)*G3 + tr + tx] = v;
    }
}

// ------------------------------- NT GEMM ------------------------------------
// C[m][n] = bias[n] + dot(A[m,0:K], W[n,0:K]);  N fixed = 768.
__global__ __launch_bounds__(256) void k_gemm(int mode, const float* __restrict__ W,
                                              const float* __restrict__ bias, int K)
{
    const float* A; float* C; int rev = 0;
    if (mode == 0)      { A = g_x;      C = g_gi_f; }
    else if (mode == 1) { A = g_x;      C = g_gi_r; rev = 1; }
    else                { A = g_seqout; C = g_G;    }

    __shared__ float As[16][68];
    __shared__ float Ws[16][68];
    int bm = blockIdx.y*64, bn = blockIdx.x*64;
    int tid = threadIdx.x;
    int tx = tid & 15, ty = tid >> 4;
    float acc[4][4];
    #pragma unroll
    for (int i=0;i<4;i++)
        #pragma unroll
        for (int j=0;j<4;j++) acc[i][j]=0.f;

    int lr = tid >> 2, lk = (tid & 3) << 2;
    const float* Ap = A + (long)(bm+lr)*K + lk;
    const float* Wp = W + (long)(bn+lr)*K + lk;

    for (int k0=0;k0<K;k0+=16){
        float4 av = *(const float4*)(Ap + k0);
        float4 wv = __ldg((const float4*)(Wp + k0));
        As[lk+0][lr]=av.x; As[lk+1][lr]=av.y; As[lk+2][lr]=av.z; As[lk+3][lr]=av.w;
        Ws[lk+0][lr]=wv.x; Ws[lk+1][lr]=wv.y; Ws[lk+2][lr]=wv.z; Ws[lk+3][lr]=wv.w;
        __syncthreads();
        #pragma unroll
        for (int k=0;k<16;k++){
            float a0=As[k][ty*4+0], a1=As[k][ty*4+1], a2=As[k][ty*4+2], a3=As[k][ty*4+3];
            float b0=Ws[k][tx*4+0], b1=Ws[k][tx*4+1], b2=Ws[k][tx*4+2], b3=Ws[k][tx*4+3];
            acc[0][0]+=a0*b0; acc[0][1]+=a0*b1; acc[0][2]+=a0*b2; acc[0][3]+=a0*b3;
            acc[1][0]+=a1*b0; acc[1][1]+=a1*b1; acc[1][2]+=a1*b2; acc[1][3]+=a1*b3;
            acc[2][0]+=a2*b0; acc[2][1]+=a2*b1; acc[2][2]+=a2*b2; acc[2][3]+=a2*b3;
            acc[3][0]+=a3*b0; acc[3][1]+=a3*b1; acc[3][2]+=a3*b2; acc[3][3]+=a3*b3;
        }
        __syncthreads();
    }
    #pragma unroll
    for (int i=0;i<4;i++){
        int m  = bm + ty*4 + i;
        int mo = m;
        if (rev){ int t = m >> 3, b = m & 7; mo = ((NN-1-t)<<3) | b; }
        #pragma unroll
        for (int j=0;j<4;j++){
            int n = bn + tx*4 + j;
            C[(long)mo*G3 + n] = acc[i][j] + __ldg(bias + n);
        }
    }
}

// -------------------------- bidirectional seq GRU ---------------------------
// (round-8/10 version; known ~366us) 128 CTAs x 256 thr. Unit=(dir,b,j): 4096
// units, 8 threads/unit (K split 32). Weights register-resident. Each CTA in
// one (dir,b) group of 8; per-group release/acquire barrier per step.
__global__ __launch_bounds__(256) void k_seqgru(const float* __restrict__ Whf,
                                                const float* __restrict__ Whr,
                                                const float* __restrict__ bhf,
                                                const float* __restrict__ bhr)
{
    int gt  = blockIdx.x*256 + threadIdx.x;
    int q   = gt & 7;
    int u   = gt >> 3;
    int j   = u & 255;
    int b   = (u >> 8) & 7;
    int dir = (u >> 11) & 1;
    const float* Wh = dir ? Whr : Whf;
    const float* bh = dir ? bhr : bhf;
    const float* gi = dir ? g_gi_r : g_gi_f;
    int k0 = q*32;
    unsigned int* ctr = &g_ctrs[(blockIdx.x >> 3)*32];   // group = (dir<<3)|b

    float wr[32], wz[32], wn[32];
    const float* pr = Wh + (long)(0*HH + j)*HH + k0;
    const float* pz = Wh + (long)(1*HH + j)*HH + k0;
    const float* pn = Wh + (long)(2*HH + j)*HH + k0;
    #pragma unroll
    for (int kk=0;kk<32;kk+=4){
        float4 v;
        v = __ldg((const float4*)(pr+kk)); wr[kk]=v.x; wr[kk+1]=v.y; wr[kk+2]=v.z; wr[kk+3]=v.w;
        v = __ldg((const float4*)(pz+kk)); wz[kk]=v.x; wz[kk+1]=v.y; wz[kk+2]=v.z; wz[kk+3]=v.w;
        v = __ldg((const float4*)(pn+kk)); wn[kk]=v.x; wn[kk+1]=v.y; wn[kk+2]=v.z; wn[kk+3]=v.w;
    }
    float br  = __ldg(bh + j);
    float bz  = __ldg(bh + HH + j);
    float bn_ = __ldg(bh + 2*HH + j);

    unsigned int target = 0;
    for (int t=0; t<NN; t++){
        const float* hc = g_h + (((t&1)<<1) | dir)*(BB*HH) + b*HH;
        float sr=0.f, sz=0.f, sn=0.f;
        #pragma unroll
        for (int kk=0;kk<32;kk+=4){
            float4 hv = __ldcg((const float4*)(hc + k0 + kk));
            sr += wr[kk]*hv.x + wr[kk+1]*hv.y + wr[kk+2]*hv.z + wr[kk+3]*hv.w;
            sz += wz[kk]*hv.x + wz[kk+1]*hv.y + wz[kk+2]*hv.z + wz[kk+3]*hv.w;
            sn += wn[kk]*hv.x + wn[kk+1]*hv.y + wn[kk+2]*hv.z + wn[kk+3]*hv.w;
        }
        #pragma unroll
        for (int off=1; off<8; off<<=1){
            sr += __shfl_xor_sync(0xffffffffu, sr, off);
            sz += __shfl_xor_sync(0xffffffffu, sz, off);
            sn += __shfl_xor_sync(0xffffffffu, sn, off);
        }
        const float* gib = gi + (long)((t<<3) + b)*G3;
        float gr = __ldg(gib + j);
        float gz = __ldg(gib + HH + j);
        float gn = __ldg(gib + 2*HH + j);
        float hold = __ldcg(hc + j);

        float r  = sigmf(gr + sr + br);
        float z  = sigmf(gz + sz + bz);
        float ng = tanhfast(gn + r*(sn + bn_));
        float hn = (1.f - z)*ng + z*hold;

        if (q == 0){
            __stcg(g_h + ((((t+1)&1)<<1) | dir)*(BB*HH) + b*HH + j, hn);
            int row = dir ? (NN-1-t) : t;
            g_seqout[(long)((row<<3)+b)*TWOH + (dir<<8) + j] = hn;
        }

        // group barrier (8 co-resident CTAs of this (dir,b) chain)
        target += 8;
        __syncthreads();
        if (threadIdx.x == 0){
            bar_arrive(ctr);
            while (ld_acq(ctr) < target) { }
        }
        __syncthreads();
    }
}

// ----------------------------- segment GRUs ---------------------------------
// 128 CTAs x 512 threads: thread = (c, k-half). Both halves accumulate the
// same (dir,b,c) outputs over disjoint k-ranges [kh*128, kh*128+128): every
// weight word is loaded exactly ONCE per CTA (no traffic increase vs 256-thr),
// but per-thread dependency chains halve and warps/SMSP doubles (2->4), hiding
// the L2 latency of the L1-missing weight stream. Partials combine through a
// 16KB smem buffer in 3 gate-phases; kh==0 threads run the GRU epilogue.
__global__ __launch_bounds__(512) void k_seg(const float* __restrict__ bhs,
                                             const float* __restrict__ h0f,
                                             const float* __restrict__ h0b,
                                             float* __restrict__ out)
{
    int i   = blockIdx.x;
    int tid = threadIdx.x;
    int c   = tid & 255;
    int kh  = tid >> 8;                  // k-half: 0 or 1

    __shared__ __align__(16) float hbuf[2][BB][SS];   // 16 KB
    __shared__ float red[16][SS];                     // 16 KB reduction buffer

    const float* h0F = h0f + (long)i*BB*SS;
    const float* h0B = h0b + (long)i*BB*SS;
    for (int idx=tid; idx<BB*SS; idx+=512){
        ((float*)hbuf[0])[idx] = h0F[idx];
        ((float*)hbuf[1])[idx] = h0B[idx];
    }

    // this thread's weight stream starts at k2 = kh*64
    const ull* wt2c = g_WT2 + c + (long)(kh*64)*G3;
    float br  = __ldg(bhs + c);
    float bz  = __ldg(bhs + SS + c);
    float bn_ = __ldg(bhs + 2*SS + c);
    __syncthreads();

    for (int t=0; t<TSEG; t++){
        int jF = min(i+t, NN-1);
        int jB = max(i-t, 0);
        const float* GF = g_G + (long)jF*BB*G3;
        const float* GB = g_G + (long)jB*BB*G3;

        ull aR[2][BB], aZ[2][BB], aN[2][BB];
        #pragma unroll
        for (int d=0;d<2;d++)
            #pragma unroll
            for (int b=0;b<BB;b++){ aR[d][b]=0ull; aZ[d][b]=0ull; aN[d][b]=0ull; }

        // 32 groups of 4 k (2 k2) within this thread's k-half
        #pragma unroll 2
        for (int g=0; g<32; g++){
            const ull* p0 = wt2c + (long)(2*g)*G3;
            const ull* p1 = p0 + G3;
            ull rA = __ldg(p0      ), rB = __ldg(p1      );
            ull zA = __ldg(p0 + 256), zB = __ldg(p1 + 256);
            ull nA = __ldg(p0 + 512), nB = __ldg(p1 + 512);
            int k = kh*128 + g*4;
            #pragma unroll
            for (int d=0;d<2;d++){
                #pragma unroll
                for (int b=0;b<BB;b++){
                    ulonglong2 h2 = *(const ulonglong2*)(&hbuf[d][b][k]);
                    ffma2(aR[d][b], rA, h2.x); ffma2(aR[d][b], rB, h2.y);
                    ffma2(aZ[d][b], zA, h2.x); ffma2(aZ[d][b], zB, h2.y);
                    ffma2(aN[d][b], nA, h2.x); ffma2(aN[d][b], nB, h2.y);
                }
            }
        }

        // horizontal sums of this half's partials
        float sR[2][BB], sZ[2][BB], sN[2][BB];
        #pragma unroll
        for (int d=0;d<2;d++)
            #pragma unroll
            for (int b=0;b<BB;b++){
                sR[d][b] = hsum2(aR[d][b]);
                sZ[d][b] = hsum2(aZ[d][b]);
                sN[d][b] = hsum2(aN[d][b]);
            }

        // cross-half reduction, one gate at a time through red[16][256]
        if (kh){
            for (int d=0;d<2;d++)
                for (int b=0;b<BB;b++) red[d*BB+b][c] = sR[d][b];
        }
        __syncthreads();
        if (!kh){
            for (int d=0;d<2;d++)
                for (int b=0;b<BB;b++) sR[d][b] += red[d*BB+b][c];
        }
        __syncthreads();
        if (kh){
            for (int d=0;d<2;d++)
                for (int b=0;b<BB;b++) red[d*BB+b][c] = sZ[d][b];
        }
        __syncthreads();
        if (!kh){
            for (int d=0;d<2;d++)
                for (int b=0;b<BB;b++) sZ[d][b] += red[d*BB+b][c];
        }
        __syncthreads();
        if (kh){
            for (int d=0;d<2;d++)
                for (int b=0;b<BB;b++) red[d*BB+b][c] = sN[d][b];
        }
        __syncthreads();
        if (!kh){
            for (int d=0;d<2;d++)
                for (int b=0;b<BB;b++) sN[d][b] += red[d*BB+b][c];
        }
        __syncthreads();

        // GRU epilogue on kh==0 threads only
        float hnew[2][BB];
        if (!kh){
            #pragma unroll
            for (int d=0;d<2;d++){
                const float* Gd = d ? GB : GF;
                #pragma unroll
                for (int b=0;b<BB;b++){
                    float hold = hbuf[d][b][c];
                    float r  = sigmf(__ldg(Gd + b*G3        + c) + sR[d][b] + br);
                    float z  = sigmf(__ldg(Gd + b*G3 + SS   + c) + sZ[d][b] + bz);
                    float ng = tanhfast(__ldg(Gd + b*G3 + 2*SS + c) + r*(sN[d][b] + bn_));
                    hnew[d][b] = (1.f - z)*ng + z*hold;
                }
            }
        }
        __syncthreads();                 // all reads of old h done
        if (!kh){
            #pragma unroll
            for (int d=0;d<2;d++)
                #pragma unroll
                for (int b=0;b<BB;b++) hbuf[d][b][c] = hnew[d][b];

            if (i+t < NN){               // forward: row=i, col=i+t
                int row = i, col = i+t;
                long idx = (long)row*NN - (long)row*(row-1)/2 + (col-row);
                float* dst = out + idx*(BB*TWOH) + c;
                #pragma unroll
                for (int b=0;b<BB;b++) dst[b*TWOH] = hnew[0][b];
            }
            if (i-t >= 0){               // backward: row=i-t, col=i
                int row = i-t, col = i;
                long idx = (long)row*NN - (long)row*(row-1)/2 + (col-row);
                float* dst = out + idx*(BB*TWOH) + SS + c;
                #pragma unroll
                for (int b=0;b<BB;b++) dst[b*TWOH] = hnew[1][b];
            }
            if (i == NN-1){
                if (t == 0){
                    float* hd = out + OUT_TRI + c;
                    #pragma unroll
                    for (int b=0;b<BB;b++) hd[b*TWOH] = hnew[0][b];
                }
                if (t == TSEG-1){
                    float* hd = out + OUT_TRI + SS + c;
                    #pragma unroll
                    for (int b=0;b<BB;b++) hd[b*TWOH] = hnew[1][b];
                }
            }
        }
        __syncthreads();                 // new h visible before next step
    }
}

// ------------------------------- launcher -----------------------------------
extern "C" void kernel_launch(void* const* d_in, const int* in_sizes, int n_in,
                              void* d_out, int out_size)
{
    const int*   tokens = (const int*)  d_in[0];
    const float* emb    = (const float*)d_in[1];
    const float* Wi_f   = (const float*)d_in[2];
    const float* Wh_f   = (const float*)d_in[3];
    const float* bi_f   = (const float*)d_in[4];
    const float* bh_f   = (const float*)d_in[5];
    const float* Wi_r   = (const float*)d_in[6];
    const float* Wh_r   = (const float*)d_in[7];
    const float* bi_r   = (const float*)d_in[8];
    const float* bh_r   = (const float*)d_in[9];
    const float* Wi_s   = (const float*)d_in[10];
    const float* Wh_s   = (const float*)d_in[11];
    const float* bi_s   = (const float*)d_in[12];
    const float* bh_s   = (const float*)d_in[13];
    const float* h0f    = (const float*)d_in[14];
    const float* h0b    = (const float*)d_in[15];
    float* out = (float*)d_out;

    k_init_embed<<<4096, 256>>>(out, tokens, emb);      // 1

    dim3 gg(G3/64, (NN*BB)/64);                          // (12, 16)
    k_gemm<<<gg, 256>>>(0, Wi_f, bi_f, EE);              // 2
    k_gemm<<<gg, 256>>>(1, Wi_r, bi_r, EE);              // 3

    k_seqgru<<<128, 256>>>(Wh_f, Wh_r, bh_f, bh_r);      // 4

    dim3 gt(SS/32, G3/32);                               // (8, 24)
    k_transpose<<<gt, 256>>>(Wh_s);                      // 5

    k_gemm<<<gg, 256>>>(2, Wi_s, bi_s, TWOH);            // 6 (profiled slot)

    k_seg<<<128, 512>>>(bh_s, h0f, h0b, out);            // 7
}

// round 14
// speedup vs baseline: 1.3354x; 1.3354x over previous
#include <cuda_runtime.h>
#include <cuda_bf16.h>
#include <cstdint>

// Problem constants
#define NN   128      // sequence length
#define BB   8        // batch
#define EE   256      // embed dim
#define HH   256      // hidden dim (seq GRU)
#define SS   256      // segment dim
#define TSEG 32       // segment window length
#define G3   768      // 3*H == 3*S (gate dim)
#define TWOH 512      // 2*H == 2*S
#define TRI_CNT  8256                  // N*(N+1)/2
#define OUT_TRI  33816576              // TRI_CNT*B*2S
#define OUT_TOTAL 33820672             // + B*2S (hidden)

typedef unsigned long long ull;

#define W_CHUNK_ULL 12288   /* 16 k2-rows x 768 ull = 96 KB */
#define HB_ULL      2048    /* 16 KB of hbuf in ull units */
#define SEG_SMEM    212992  /* (2048 + 2*12288) * 8 bytes */

// ------------------------------- scratch -----------------------------------
__device__ float g_x[NN*BB*EE];          // embedded inputs (N*B, E)
__device__ float g_gi_f[NN*BB*G3];       // forward  seq input gates
__device__ float g_gi_r[NN*BB*G3];       // backward seq input gates (step-indexed)
__device__ float g_seqout[NN*BB*TWOH];   // bidirectional GRU outputs (N,B,2H)
__device__ float g_G[NN*BB*G3];          // segment input gates per column j
__device__ float g_h[2*2*BB*HH];         // [parity][dir][b][h] double-buffered seq state
__device__ ull   g_WT2[(SS/2)*G3];       // transposed+paired seg weights:
                                         //   WT2[k2][gate*256+c] = (w[2k2][c], w[2k2+1][c])
__device__ unsigned int g_ctrs[16*32];   // per-(dir,b) barrier counters, 128B apart

__device__ __forceinline__ float sigmf(float x)    { return 1.f/(1.f+__expf(-x)); }
__device__ __forceinline__ float tanhfast(float x) { return 2.f/(1.f+__expf(-2.f*x)) - 1.f; }

// packed fp32x2 FMA (Blackwell FFMA2): d = a*b + d, per 32-bit lane
__device__ __forceinline__ void ffma2(ull &d, ull a, ull b){
    asm("fma.rn.f32x2 %0, %1, %2, %0;" : "+l"(d) : "l"(a), "l"(b));
}
__device__ __forceinline__ float hsum2(ull v){
    float lo, hi;
    asm("mov.b64 {%0,%1}, %2;" : "=f"(lo), "=f"(hi) : "l"(v));
    return lo + hi;
}
__device__ __forceinline__ ull pack2(float lo, float hi){
    ull d;
    asm("mov.b64 %0, {%1,%2};" : "=l"(d) : "f"(lo), "f"(hi));
    return d;
}
__device__ __forceinline__ uint32_t smem_u32(const void* p){
    uint32_t a;
    asm("{ .reg .u64 t; cvta.to.shared.u64 t, %1; cvt.u32.u64 %0, t; }"
        : "=r"(a) : "l"(p));
    return a;
}

// release arrive / acquire poll for the group barriers (no full membar)
__device__ __forceinline__ void bar_arrive(unsigned int* ctr){
    asm volatile("red.release.gpu.global.add.u32 [%0], 1;" :: "l"(ctr) : "memory");
}
__device__ __forceinline__ unsigned int ld_acq(const unsigned int* p){
    unsigned int v;
    asm volatile("ld.acquire.gpu.global.u32 %0, [%1];" : "=r"(v) : "l"(p) : "memory");
    return v;
}

// cp.async helpers: 256 threads move one 96KB chunk (24 x 16B per thread)
__device__ __forceinline__ void load_chunk(ull* wdst, const ull* gsrc, int tid){
    uint32_t s = smem_u32(wdst) + tid*16;
    const char* g = (const char*)gsrc + tid*16;
    #pragma unroll
    for (int j=0;j<24;j++){
        asm volatile("cp.async.cg.shared.global [%0], [%1], 16;"
                     :: "r"(s + j*4096), "l"(g + j*4096));
    }
    asm volatile("cp.async.commit_group;" ::: "memory");
}

// ----------------------- init (zero) + embedding ----------------------------
__global__ void k_init_embed(float* __restrict__ out,
                             const int* __restrict__ tokens,
                             const float* __restrict__ emb)
{
    long tid    = (long)blockIdx.x*blockDim.x + threadIdx.x;
    long stride = (long)gridDim.x*blockDim.x;
    float4 z = make_float4(0.f,0.f,0.f,0.f);
    float4* o4 = (float4*)out;
    for (long i=tid; i < OUT_TOTAL/4; i+=stride) o4[i] = z;
    if (tid < 2*2*BB*HH) g_h[tid] = 0.f;
    if (tid < 16*32)     g_ctrs[tid] = 0u;
    // embedding: blocks 0..1023 each copy one (n,b) row of 256 floats
    if (blockIdx.x < NN*BB){
        int m = blockIdx.x;
        int tok = tokens[m];
        g_x[(long)m*EE + threadIdx.x] = __ldg(emb + (long)tok*EE + threadIdx.x);
    }
}

// --------------------- transpose + pair segment weights ---------------------
// Whs[row][k] (768 x 256) -> g_WT2[k2][row] with k-pairs packed in one 8B word.
__global__ __launch_bounds__(256) void k_transpose(const float* __restrict__ Whs)
{
    __shared__ float tile[32][33];
    int tk = blockIdx.x*32;          // k-block   (0..224), 32 k = 16 k2
    int tr = blockIdx.y*32;          // row-block (0..736)
    int tx = threadIdx.x & 31, ty = threadIdx.x >> 5;   // 32 x 8
    #pragma unroll
    for (int r=ty; r<32; r+=8)
        tile[r][tx] = __ldg(Whs + (long)(tr+r)*SS + tk + tx);
    __syncthreads();
    #pragma unroll
    for (int k2=ty; k2<16; k2+=8){
        ull v = pack2(tile[tx][2*k2], tile[tx][2*k2+1]);
        g_WT2[(long)((tk>>1)+k2)*G3 + tr + tx] = v;
    }
}

// ------------------------------- NT GEMM ------------------------------------
// C[m][n] = bias[n] + dot(A[m,0:K], W[n,0:K]);  N fixed = 768.
__global__ __launch_bounds__(256) void k_gemm(int mode, const float* __restrict__ W,
                                              const float* __restrict__ bias, int K)
{
    const float* A; float* C; int rev = 0;
    if (mode == 0)      { A = g_x;      C = g_gi_f; }
    else if (mode == 1) { A = g_x;      C = g_gi_r; rev = 1; }
    else                { A = g_seqout; C = g_G;    }

    __shared__ float As[16][68];
    __shared__ float Ws[16][68];
    int bm = blockIdx.y*64, bn = blockIdx.x*64;
    int tid = threadIdx.x;
    int tx = tid & 15, ty = tid >> 4;
    float acc[4][4];
    #pragma unroll
    for (int i=0;i<4;i++)
        #pragma unroll
        for (int j=0;j<4;j++) acc[i][j]=0.f;

    int lr = tid >> 2, lk = (tid & 3) << 2;
    const float* Ap = A + (long)(bm+lr)*K + lk;
    const float* Wp = W + (long)(bn+lr)*K + lk;

    for (int k0=0;k0<K;k0+=16){
        float4 av = *(const float4*)(Ap + k0);
        float4 wv = __ldg((const float4*)(Wp + k0));
        As[lk+0][lr]=av.x; As[lk+1][lr]=av.y; As[lk+2][lr]=av.z; As[lk+3][lr]=av.w;
        Ws[lk+0][lr]=wv.x; Ws[lk+1][lr]=wv.y; Ws[lk+2][lr]=wv.z; Ws[lk+3][lr]=wv.w;
        __syncthreads();
        #pragma unroll
        for (int k=0;k<16;k++){
            float a0=As[k][ty*4+0], a1=As[k][ty*4+1], a2=As[k][ty*4+2], a3=As[k][ty*4+3];
            float b0=Ws[k][tx*4+0], b1=Ws[k][tx*4+1], b2=Ws[k][tx*4+2], b3=Ws[k][tx*4+3];
            acc[0][0]+=a0*b0; acc[0][1]+=a0*b1; acc[0][2]+=a0*b2; acc[0][3]+=a0*b3;
            acc[1][0]+=a1*b0; acc[1][1]+=a1*b1; acc[1][2]+=a1*b2; acc[1][3]+=a1*b3;
            acc[2][0]+=a2*b0; acc[2][1]+=a2*b1; acc[2][2]+=a2*b2; acc[2][3]+=a2*b3;
            acc[3][0]+=a3*b0; acc[3][1]+=a3*b1; acc[3][2]+=a3*b2; acc[3][3]+=a3*b3;
        }
        __syncthreads();
    }
    #pragma unroll
    for (int i=0;i<4;i++){
        int m  = bm + ty*4 + i;
        int mo = m;
        if (rev){ int t = m >> 3, b = m & 7; mo = ((NN-1-t)<<3) | b; }
        #pragma unroll
        for (int j=0;j<4;j++){
            int n = bn + tx*4 + j;
            C[(long)mo*G3 + n] = acc[i][j] + __ldg(bias + n);
        }
    }
}

// -------------------------- bidirectional seq GRU ---------------------------
// (round-8/10 version; known ~366us) 128 CTAs x 256 thr. Unit=(dir,b,j): 4096
// units, 8 threads/unit (K split 32). Weights register-resident. Each CTA in
// one (dir,b) group of 8; per-group release/acquire barrier per step.
__global__ __launch_bounds__(256) void k_seqgru(const float* __restrict__ Whf,
                                                const float* __restrict__ Whr,
                                                const float* __restrict__ bhf,
                                                const float* __restrict__ bhr)
{
    int gt  = blockIdx.x*256 + threadIdx.x;
    int q   = gt & 7;
    int u   = gt >> 3;
    int j   = u & 255;
    int b   = (u >> 8) & 7;
    int dir = (u >> 11) & 1;
    const float* Wh = dir ? Whr : Whf;
    const float* bh = dir ? bhr : bhf;
    const float* gi = dir ? g_gi_r : g_gi_f;
    int k0 = q*32;
    unsigned int* ctr = &g_ctrs[(blockIdx.x >> 3)*32];   // group = (dir<<3)|b

    float wr[32], wz[32], wn[32];
    const float* pr = Wh + (long)(0*HH + j)*HH + k0;
    const float* pz = Wh + (long)(1*HH + j)*HH + k0;
    const float* pn = Wh + (long)(2*HH + j)*HH + k0;
    #pragma unroll
    for (int kk=0;kk<32;kk+=4){
        float4 v;
        v = __ldg((const float4*)(pr+kk)); wr[kk]=v.x; wr[kk+1]=v.y; wr[kk+2]=v.z; wr[kk+3]=v.w;
        v = __ldg((const float4*)(pz+kk)); wz[kk]=v.x; wz[kk+1]=v.y; wz[kk+2]=v.z; wz[kk+3]=v.w;
        v = __ldg((const float4*)(pn+kk)); wn[kk]=v.x; wn[kk+1]=v.y; wn[kk+2]=v.z; wn[kk+3]=v.w;
    }
    float br  = __ldg(bh + j);
    float bz  = __ldg(bh + HH + j);
    float bn_ = __ldg(bh + 2*HH + j);

    unsigned int target = 0;
    for (int t=0; t<NN; t++){
        const float* hc = g_h + (((t&1)<<1) | dir)*(BB*HH) + b*HH;
        float sr=0.f, sz=0.f, sn=0.f;
        #pragma unroll
        for (int kk=0;kk<32;kk+=4){
            float4 hv = __ldcg((const float4*)(hc + k0 + kk));
            sr += wr[kk]*hv.x + wr[kk+1]*hv.y + wr[kk+2]*hv.z + wr[kk+3]*hv.w;
            sz += wz[kk]*hv.x + wz[kk+1]*hv.y + wz[kk+2]*hv.z + wz[kk+3]*hv.w;
            sn += wn[kk]*hv.x + wn[kk+1]*hv.y + wn[kk+2]*hv.z + wn[kk+3]*hv.w;
        }
        #pragma unroll
        for (int off=1; off<8; off<<=1){
            sr += __shfl_xor_sync(0xffffffffu, sr, off);
            sz += __shfl_xor_sync(0xffffffffu, sz, off);
            sn += __shfl_xor_sync(0xffffffffu, sn, off);
        }
        const float* gib = gi + (long)((t<<3) + b)*G3;
        float gr = __ldg(gib + j);
        float gz = __ldg(gib + HH + j);
        float gn = __ldg(gib + 2*HH + j);
        float hold = __ldcg(hc + j);

        float r  = sigmf(gr + sr + br);
        float z  = sigmf(gz + sz + bz);
        float ng = tanhfast(gn + r*(sn + bn_));
        float hn = (1.f - z)*ng + z*hold;

        if (q == 0){
            __stcg(g_h + ((((t+1)&1)<<1) | dir)*(BB*HH) + b*HH + j, hn);
            int row = dir ? (NN-1-t) : t;
            g_seqout[(long)((row<<3)+b)*TWOH + (dir<<8) + j] = hn;
        }

        // group barrier (8 co-resident CTAs of this (dir,b) chain)
        target += 8;
        __syncthreads();
        if (threadIdx.x == 0){
            bar_arrive(ctr);
            while (ld_acq(ctr) < target) { }
        }
        __syncthreads();
    }
}

// ----------------------------- segment GRUs ---------------------------------
// 128 CTAs x 256 threads: CTA i handles BOTH direction chains for start i;
// thread c owns gate column c for all 8 batch rows of both chains (96 acc
// regs). The 786KB/step weight stream is staged through smem with cp.async
// DOUBLE BUFFERING (8 chunks of 96KB, 2 buffers): LDGSTS has no register
// target, so L2 latency is fully pipelined away; the FFMA2 loop reads weights
// as coalesced conflict-free LDS.64. Chunks repeat every step, so the
// prefetch ring wraps across steps with a constant wait_group 1.
__global__ __launch_bounds__(256) void k_seg(const float* __restrict__ bhs,
                                             const float* __restrict__ h0f,
                                             const float* __restrict__ h0b,
                                             float* __restrict__ out)
{
    extern __shared__ __align__(16) ull dsm[];
    float (*hbuf)[BB][SS] = (float (*)[BB][SS])dsm;     // [2][8][256] = 16KB
    ull* wbuf0 = dsm + HB_ULL;                          // 96KB chunk buffer 0
    ull* wbuf1 = dsm + HB_ULL + W_CHUNK_ULL;            // 96KB chunk buffer 1

    int i = blockIdx.x;
    int c = threadIdx.x;

    // prologue: kick chunks 0 and 1 before anything else
    load_chunk(wbuf0, g_WT2,               c);
    load_chunk(wbuf1, g_WT2 + W_CHUNK_ULL, c);

    const float* h0F = h0f + (long)i*BB*SS;
    const float* h0B = h0b + (long)i*BB*SS;
    for (int idx=c; idx<BB*SS; idx+=256){
        ((float*)hbuf[0])[idx] = h0F[idx];
        ((float*)hbuf[1])[idx] = h0B[idx];
    }

    float br  = __ldg(bhs + c);
    float bz  = __ldg(bhs + SS + c);
    float bn_ = __ldg(bhs + 2*SS + c);
    __syncthreads();

    for (int t=0; t<TSEG; t++){
        int jF = min(i+t, NN-1);
        int jB = max(i-t, 0);
        const float* GF = g_G + (long)jF*BB*G3;
        const float* GB = g_G + (long)jB*BB*G3;

        ull aR[2][BB], aZ[2][BB], aN[2][BB];
        #pragma unroll
        for (int d=0;d<2;d++)
            #pragma unroll
            for (int b=0;b<BB;b++){ aR[d][b]=0ull; aZ[d][b]=0ull; aN[d][b]=0ull; }

        // 8 chunks of 16 k2 (32 k) each; buffer parity = ck & 1
        for (int ck=0; ck<8; ck++){
            asm volatile("cp.async.wait_group 1;" ::: "memory");
            __syncthreads();
            const ull* w = (ck & 1) ? wbuf1 : wbuf0;

            #pragma unroll
            for (int g2=0; g2<8; g2++){
                ull rA = w[(2*g2  )*G3       + c];
                ull rB = w[(2*g2+1)*G3       + c];
                ull zA = w[(2*g2  )*G3 + 256 + c];
                ull zB = w[(2*g2+1)*G3 + 256 + c];
                ull nA = w[(2*g2  )*G3 + 512 + c];
                ull nB = w[(2*g2+1)*G3 + 512 + c];
                int k = ck*32 + g2*4;
                #pragma unroll
                for (int d=0;d<2;d++){
                    #pragma unroll
                    for (int b=0;b<BB;b++){
                        ulonglong2 h2 = *(const ulonglong2*)(&hbuf[d][b][k]);
                        ffma2(aR[d][b], rA, h2.x); ffma2(aR[d][b], rB, h2.y);
                        ffma2(aZ[d][b], zA, h2.x); ffma2(aZ[d][b], zB, h2.y);
                        ffma2(aN[d][b], nA, h2.x); ffma2(aN[d][b], nB, h2.y);
                    }
                }
            }
            __syncthreads();   // everyone done reading this buffer
            // prefetch chunk (ck+2) mod 8 (wraps into next step's stream)
            int nx = (ck + 2) & 7;
            load_chunk((ck & 1) ? wbuf1 : wbuf0, g_WT2 + (long)nx*W_CHUNK_ULL, c);
        }

        float hnew[2][BB];
        #pragma unroll
        for (int d=0;d<2;d++){
            const float* Gd = d ? GB : GF;
            #pragma unroll
            for (int b=0;b<BB;b++){
                float sr = hsum2(aR[d][b]);
                float sz = hsum2(aZ[d][b]);
                float sn = hsum2(aN[d][b]);
                float hold = hbuf[d][b][c];
                float r  = sigmf(__ldg(Gd + b*G3        + c) + sr + br);
                float z  = sigmf(__ldg(Gd + b*G3 + SS   + c) + sz + bz);
                float ng = tanhfast(__ldg(Gd + b*G3 + 2*SS + c) + r*(sn + bn_));
                hnew[d][b] = (1.f - z)*ng + z*hold;
            }
        }
        __syncthreads();                 // all reads of old h done
        #pragma unroll
        for (int d=0;d<2;d++)
            #pragma unroll
            for (int b=0;b<BB;b++) hbuf[d][b][c] = hnew[d][b];

        if (i+t < NN){                   // forward: row=i, col=i+t
            int row = i, col = i+t;
            long idx = (long)row*NN - (long)row*(row-1)/2 + (col-row);
            float* dst = out + idx*(BB*TWOH) + c;
            #pragma unroll
            for (int b=0;b<BB;b++) dst[b*TWOH] = hnew[0][b];
        }
        if (i-t >= 0){                   // backward: row=i-t, col=i
            int row = i-t, col = i;
            long idx = (long)row*NN - (long)row*(row-1)/2 + (col-row);
            float* dst = out + idx*(BB*TWOH) + SS + c;
            #pragma unroll
            for (int b=0;b<BB;b++) dst[b*TWOH] = hnew[1][b];
        }
        if (i == NN-1){
            if (t == 0){
                float* hd = out + OUT_TRI + c;
                #pragma unroll
                for (int b=0;b<BB;b++) hd[b*TWOH] = hnew[0][b];
            }
            if (t == TSEG-1){
                float* hd = out + OUT_TRI + SS + c;
                #pragma unroll
                for (int b=0;b<BB;b++) hd[b*TWOH] = hnew[1][b];
            }
        }
        __syncthreads();                 // new h visible before next step
    }
    // drain outstanding prefetches before exit
    asm volatile("cp.async.wait_group 0;" ::: "memory");
}

// ------------------------------- launcher -----------------------------------
extern "C" void kernel_launch(void* const* d_in, const int* in_sizes, int n_in,
                              void* d_out, int out_size)
{
    const int*   tokens = (const int*)  d_in[0];
    const float* emb    = (const float*)d_in[1];
    const float* Wi_f   = (const float*)d_in[2];
    const float* Wh_f   = (const float*)d_in[3];
    const float* bi_f   = (const float*)d_in[4];
    const float* bh_f   = (const float*)d_in[5];
    const float* Wi_r   = (const float*)d_in[6];
    const float* Wh_r   = (const float*)d_in[7];
    const float* bi_r   = (const float*)d_in[8];
    const float* bh_r   = (const float*)d_in[9];
    const float* Wi_s   = (const float*)d_in[10];
    const float* Wh_s   = (const float*)d_in[11];
    const float* bi_s   = (const float*)d_in[12];
    const float* bh_s   = (const float*)d_in[13];
    const float* h0f    = (const float*)d_in[14];
    const float* h0b    = (const float*)d_in[15];
    float* out = (float*)d_out;

    cudaFuncSetAttribute(k_seg, cudaFuncAttributeMaxDynamicSharedMemorySize, SEG_SMEM);

    k_init_embed<<<4096, 256>>>(out, tokens, emb);      // 1

    dim3 gg(G3/64, (NN*BB)/64);                          // (12, 16)
    k_gemm<<<gg, 256>>>(0, Wi_f, bi_f, EE);              // 2
    k_gemm<<<gg, 256>>>(1, Wi_r, bi_r, EE);              // 3

    k_seqgru<<<128, 256>>>(Wh_f, Wh_r, bh_f, bh_r);      // 4

    dim3 gt(SS/32, G3/32);                               // (8, 24)
    k_transpose<<<gt, 256>>>(Wh_s);                      // 5

    k_gemm<<<gg, 256>>>(2, Wi_s, bi_s, TWOH);            // 6 (profiled slot)

    k_seg<<<128, 256, SEG_SMEM>>>(bh_s, h0f, h0b, out);  // 7
}

// round 15
// speedup vs baseline: 1.4962x; 1.1204x over previous
#include <cuda_runtime.h>
#include <cuda_bf16.h>
#include <cstdint>

// Problem constants
#define NN   128      // sequence length
#define BB   8        // batch
#define EE   256      // embed dim
#define HH   256      // hidden dim (seq GRU)
#define SS   256      // segment dim
#define TSEG 32       // segment window length
#define G3   768      // 3*H == 3*S (gate dim)
#define TWOH 512      // 2*H == 2*S
#define TRI_CNT  8256                  // N*(N+1)/2
#define OUT_TRI  33816576              // TRI_CNT*B*2S
#define OUT_TOTAL 33820672             // + B*2S (hidden)

typedef unsigned long long ull;

#define W_CHUNK_ULL 12288   /* 16 k2-rows x 768 ull = 96 KB */
#define HB_ULL      2048    /* 16 KB of hbuf in ull units */
#define SEG_SMEM    212992  /* (2048 + 2*12288) * 8 bytes */

// ------------------------------- scratch -----------------------------------
__device__ float g_x[NN*BB*EE];          // embedded inputs (N*B, E)
__device__ float g_gi_f[NN*BB*G3];       // forward  seq input gates
__device__ float g_gi_r[NN*BB*G3];       // backward seq input gates (step-indexed)
__device__ float g_seqout[NN*BB*TWOH];   // bidirectional GRU outputs (N,B,2H)
__device__ float g_G[NN*BB*G3];          // segment input gates per column j
__device__ float g_h[2*2*BB*HH];         // [parity][dir][b][h] double-buffered seq state
__device__ ull   g_WT2[(SS/2)*G3];       // transposed+paired seg weights:
                                         //   WT2[k2][gate*256+c] = (w[2k2][c], w[2k2+1][c])
__device__ unsigned int g_ctrs[16*32];   // per-(dir,b) barrier counters, 128B apart

__device__ __forceinline__ float sigmf(float x)    { return 1.f/(1.f+__expf(-x)); }
__device__ __forceinline__ float tanhfast(float x) { return 2.f/(1.f+__expf(-2.f*x)) - 1.f; }

// packed fp32x2 FMA (Blackwell FFMA2): d = a*b + d, per 32-bit lane
__device__ __forceinline__ void ffma2(ull &d, ull a, ull b){
    asm("fma.rn.f32x2 %0, %1, %2, %0;" : "+l"(d) : "l"(a), "l"(b));
}
__device__ __forceinline__ float hsum2(ull v){
    float lo, hi;
    asm("mov.b64 {%0,%1}, %2;" : "=f"(lo), "=f"(hi) : "l"(v));
    return lo + hi;
}
__device__ __forceinline__ ull pack2(float lo, float hi){
    ull d;
    asm("mov.b64 %0, {%1,%2};" : "=l"(d) : "f"(lo), "f"(hi));
    return d;
}
__device__ __forceinline__ uint32_t smem_u32(const void* p){
    uint32_t a;
    asm("{ .reg .u64 t; cvta.to.shared.u64 t, %1; cvt.u32.u64 %0, t; }"
        : "=r"(a) : "l"(p));
    return a;
}

// release arrive / acquire poll for the group barriers (no full membar)
__device__ __forceinline__ void bar_arrive(unsigned int* ctr){
    asm volatile("red.release.gpu.global.add.u32 [%0], 1;" :: "l"(ctr) : "memory");
}
__device__ __forceinline__ unsigned int ld_acq(const unsigned int* p){
    unsigned int v;
    asm volatile("ld.acquire.gpu.global.u32 %0, [%1];" : "=r"(v) : "l"(p) : "memory");
    return v;
}

// cp.async: 512 threads move one 96KB chunk (12 x 16B per thread)
__device__ __forceinline__ void load_chunk(ull* wdst, const ull* gsrc, int tid){
    uint32_t s = smem_u32(wdst) + tid*16;
    const char* g = (const char*)gsrc + tid*16;
    #pragma unroll
    for (int j=0;j<12;j++){
        asm volatile("cp.async.cg.shared.global [%0], [%1], 16;"
                     :: "r"(s + j*8192), "l"(g + j*8192));
    }
    asm volatile("cp.async.commit_group;" ::: "memory");
}

// ----------------------- init (zero) + embedding ----------------------------
__global__ void k_init_embed(float* __restrict__ out,
                             const int* __restrict__ tokens,
                             const float* __restrict__ emb)
{
    long tid    = (long)blockIdx.x*blockDim.x + threadIdx.x;
    long stride = (long)gridDim.x*blockDim.x;
    float4 z = make_float4(0.f,0.f,0.f,0.f);
    float4* o4 = (float4*)out;
    for (long i=tid; i < OUT_TOTAL/4; i+=stride) o4[i] = z;
    if (tid < 2*2*BB*HH) g_h[tid] = 0.f;
    if (tid < 16*32)     g_ctrs[tid] = 0u;
    // embedding: blocks 0..1023 each copy one (n,b) row of 256 floats
    if (blockIdx.x < NN*BB){
        int m = blockIdx.x;
        int tok = tokens[m];
        g_x[(long)m*EE + threadIdx.x] = __ldg(emb + (long)tok*EE + threadIdx.x);
    }
}

// --------------------- transpose + pair segment weights ---------------------
// Whs[row][k] (768 x 256) -> g_WT2[k2][row] with k-pairs packed in one 8B word.
__global__ __launch_bounds__(256) void k_transpose(const float* __restrict__ Whs)
{
    __shared__ float tile[32][33];
    int tk = blockIdx.x*32;          // k-block   (0..224), 32 k = 16 k2
    int tr = blockIdx.y*32;          // row-block (0..736)
    int tx = threadIdx.x & 31, ty = threadIdx.x >> 5;   // 32 x 8
    #pragma unroll
    for (int r=ty; r<32; r+=8)
        tile[r][tx] = __ldg(Whs + (long)(tr+r)*SS + tk + tx);
    __syncthreads();
    #pragma unroll
    for (int k2=ty; k2<16; k2+=8){
        ull v = pack2(tile[tx][2*k2], tile[tx][2*k2+1]);
        g_WT2[(long)((tk>>1)+k2)*G3 + tr + tx] = v;
    }
}

// ------------------------------- NT GEMM ------------------------------------
// C[m][n] = bias[n] + dot(A[m,0:K], W[n,0:K]);  N fixed = 768.
__global__ __launch_bounds__(256) void k_gemm(int mode, const float* __restrict__ W,
                                              const float* __restrict__ bias, int K)
{
    const float* A; float* C; int rev = 0;
    if (mode == 0)      { A = g_x;      C = g_gi_f; }
    else if (mode == 1) { A = g_x;      C = g_gi_r; rev = 1; }
    else                { A = g_seqout; C = g_G;    }

    __shared__ float As[16][68];
    __shared__ float Ws[16][68];
    int bm = blockIdx.y*64, bn = blockIdx.x*64;
    int tid = threadIdx.x;
    int tx = tid & 15, ty = tid >> 4;
    float acc[4][4];
    #pragma unroll
    for (int i=0;i<4;i++)
        #pragma unroll
        for (int j=0;j<4;j++) acc[i][j]=0.f;

    int lr = tid >> 2, lk = (tid & 3) << 2;
    const float* Ap = A + (long)(bm+lr)*K + lk;
    const float* Wp = W + (long)(bn+lr)*K + lk;

    for (int k0=0;k0<K;k0+=16){
        float4 av = *(const float4*)(Ap + k0);
        float4 wv = __ldg((const float4*)(Wp + k0));
        As[lk+0][lr]=av.x; As[lk+1][lr]=av.y; As[lk+2][lr]=av.z; As[lk+3][lr]=av.w;
        Ws[lk+0][lr]=wv.x; Ws[lk+1][lr]=wv.y; Ws[lk+2][lr]=wv.z; Ws[lk+3][lr]=wv.w;
        __syncthreads();
        #pragma unroll
        for (int k=0;k<16;k++){
            float a0=As[k][ty*4+0], a1=As[k][ty*4+1], a2=As[k][ty*4+2], a3=As[k][ty*4+3];
            float b0=Ws[k][tx*4+0], b1=Ws[k][tx*4+1], b2=Ws[k][tx*4+2], b3=Ws[k][tx*4+3];
            acc[0][0]+=a0*b0; acc[0][1]+=a0*b1; acc[0][2]+=a0*b2; acc[0][3]+=a0*b3;
            acc[1][0]+=a1*b0; acc[1][1]+=a1*b1; acc[1][2]+=a1*b2; acc[1][3]+=a1*b3;
            acc[2][0]+=a2*b0; acc[2][1]+=a2*b1; acc[2][2]+=a2*b2; acc[2][3]+=a2*b3;
            acc[3][0]+=a3*b0; acc[3][1]+=a3*b1; acc[3][2]+=a3*b2; acc[3][3]+=a3*b3;
        }
        __syncthreads();
    }
    #pragma unroll
    for (int i=0;i<4;i++){
        int m  = bm + ty*4 + i;
        int mo = m;
        if (rev){ int t = m >> 3, b = m & 7; mo = ((NN-1-t)<<3) | b; }
        #pragma unroll
        for (int j=0;j<4;j++){
            int n = bn + tx*4 + j;
            C[(long)mo*G3 + n] = acc[i][j] + __ldg(bias + n);
        }
    }
}

// -------------------------- bidirectional seq GRU ---------------------------
// (round-8/10 version; known ~366us) 128 CTAs x 256 thr. Unit=(dir,b,j): 4096
// units, 8 threads/unit (K split 32). Weights register-resident. Each CTA in
// one (dir,b) group of 8; per-group release/acquire barrier per step.
__global__ __launch_bounds__(256) void k_seqgru(const float* __restrict__ Whf,
                                                const float* __restrict__ Whr,
                                                const float* __restrict__ bhf,
                                                const float* __restrict__ bhr)
{
    int gt  = blockIdx.x*256 + threadIdx.x;
    int q   = gt & 7;
    int u   = gt >> 3;
    int j   = u & 255;
    int b   = (u >> 8) & 7;
    int dir = (u >> 11) & 1;
    const float* Wh = dir ? Whr : Whf;
    const float* bh = dir ? bhr : bhf;
    const float* gi = dir ? g_gi_r : g_gi_f;
    int k0 = q*32;
    unsigned int* ctr = &g_ctrs[(blockIdx.x >> 3)*32];   // group = (dir<<3)|b

    float wr[32], wz[32], wn[32];
    const float* pr = Wh + (long)(0*HH + j)*HH + k0;
    const float* pz = Wh + (long)(1*HH + j)*HH + k0;
    const float* pn = Wh + (long)(2*HH + j)*HH + k0;
    #pragma unroll
    for (int kk=0;kk<32;kk+=4){
        float4 v;
        v = __ldg((const float4*)(pr+kk)); wr[kk]=v.x; wr[kk+1]=v.y; wr[kk+2]=v.z; wr[kk+3]=v.w;
        v = __ldg((const float4*)(pz+kk)); wz[kk]=v.x; wz[kk+1]=v.y; wz[kk+2]=v.z; wz[kk+3]=v.w;
        v = __ldg((const float4*)(pn+kk)); wn[kk]=v.x; wn[kk+1]=v.y; wn[kk+2]=v.z; wn[kk+3]=v.w;
    }
    float br  = __ldg(bh + j);
    float bz  = __ldg(bh + HH + j);
    float bn_ = __ldg(bh + 2*HH + j);

    unsigned int target = 0;
    for (int t=0; t<NN; t++){
        const float* hc = g_h + (((t&1)<<1) | dir)*(BB*HH) + b*HH;
        float sr=0.f, sz=0.f, sn=0.f;
        #pragma unroll
        for (int kk=0;kk<32;kk+=4){
            float4 hv = __ldcg((const float4*)(hc + k0 + kk));
            sr += wr[kk]*hv.x + wr[kk+1]*hv.y + wr[kk+2]*hv.z + wr[kk+3]*hv.w;
            sz += wz[kk]*hv.x + wz[kk+1]*hv.y + wz[kk+2]*hv.z + wz[kk+3]*hv.w;
            sn += wn[kk]*hv.x + wn[kk+1]*hv.y + wn[kk+2]*hv.z + wn[kk+3]*hv.w;
        }
        #pragma unroll
        for (int off=1; off<8; off<<=1){
            sr += __shfl_xor_sync(0xffffffffu, sr, off);
            sz += __shfl_xor_sync(0xffffffffu, sz, off);
            sn += __shfl_xor_sync(0xffffffffu, sn, off);
        }
        const float* gib = gi + (long)((t<<3) + b)*G3;
        float gr = __ldg(gib + j);
        float gz = __ldg(gib + HH + j);
        float gn = __ldg(gib + 2*HH + j);
        float hold = __ldcg(hc + j);

        float r  = sigmf(gr + sr + br);
        float z  = sigmf(gz + sz + bz);
        float ng = tanhfast(gn + r*(sn + bn_));
        float hn = (1.f - z)*ng + z*hold;

        if (q == 0){
            __stcg(g_h + ((((t+1)&1)<<1) | dir)*(BB*HH) + b*HH + j, hn);
            int row = dir ? (NN-1-t) : t;
            g_seqout[(long)((row<<3)+b)*TWOH + (dir<<8) + j] = hn;
        }

        // group barrier (8 co-resident CTAs of this (dir,b) chain)
        target += 8;
        __syncthreads();
        if (threadIdx.x == 0){
            bar_arrive(ctr);
            while (ld_acq(ctr) < target) { }
        }
        __syncthreads();
    }
}

// ----------------------------- segment GRUs ---------------------------------
// 128 CTAs x 512 threads: thread = (c, b-half). Thread owns gate column c for
// batch rows [bh*4, bh*4+4) of BOTH direction chains (24 fp32x2 accumulators).
// No cross-thread reduction needed: everything partitions by b. Weights staged
// via cp.async double buffering (smem reads nearly free); warps/SMSP = 4
// hides LDS->FFMA2 latency that bound the 256-thread version.
__global__ __launch_bounds__(512) void k_seg(const float* __restrict__ bhs,
                                             const float* __restrict__ h0f,
                                             const float* __restrict__ h0b,
                                             float* __restrict__ out)
{
    extern __shared__ __align__(16) ull dsm[];
    float (*hbuf)[BB][SS] = (float (*)[BB][SS])dsm;     // [2][8][256] = 16KB
    ull* wbuf0 = dsm + HB_ULL;                          // 96KB chunk buffer 0
    ull* wbuf1 = dsm + HB_ULL + W_CHUNK_ULL;            // 96KB chunk buffer 1

    int i   = blockIdx.x;
    int tid = threadIdx.x;
    int c   = tid & 255;
    int bh  = tid >> 8;              // batch half: rows [bh*4, bh*4+4)
    int b0  = bh*4;

    // prologue: kick chunks 0 and 1 before anything else
    load_chunk(wbuf0, g_WT2,               tid);
    load_chunk(wbuf1, g_WT2 + W_CHUNK_ULL, tid);

    const float* h0F = h0f + (long)i*BB*SS;
    const float* h0B = h0b + (long)i*BB*SS;
    for (int idx=tid; idx<BB*SS; idx+=512){
        ((float*)hbuf[0])[idx] = h0F[idx];
        ((float*)hbuf[1])[idx] = h0B[idx];
    }

    float br  = __ldg(bhs + c);
    float bz  = __ldg(bhs + SS + c);
    float bn_ = __ldg(bhs + 2*SS + c);
    __syncthreads();

    for (int t=0; t<TSEG; t++){
        int jF = min(i+t, NN-1);
        int jB = max(i-t, 0);
        const float* GF = g_G + (long)jF*BB*G3;
        const float* GB = g_G + (long)jB*BB*G3;

        ull aR[2][4], aZ[2][4], aN[2][4];
        #pragma unroll
        for (int d=0;d<2;d++)
            #pragma unroll
            for (int b=0;b<4;b++){ aR[d][b]=0ull; aZ[d][b]=0ull; aN[d][b]=0ull; }

        // 8 chunks of 16 k2 (32 k) each; buffer parity = ck & 1
        for (int ck=0; ck<8; ck++){
            asm volatile("cp.async.wait_group 1;" ::: "memory");
            __syncthreads();
            const ull* w = (ck & 1) ? wbuf1 : wbuf0;

            #pragma unroll
            for (int g2=0; g2<8; g2++){
                ull rA = w[(2*g2  )*G3       + c];
                ull rB = w[(2*g2+1)*G3       + c];
                ull zA = w[(2*g2  )*G3 + 256 + c];
                ull zB = w[(2*g2+1)*G3 + 256 + c];
                ull nA = w[(2*g2  )*G3 + 512 + c];
                ull nB = w[(2*g2+1)*G3 + 512 + c];
                int k = ck*32 + g2*4;
                #pragma unroll
                for (int d=0;d<2;d++){
                    #pragma unroll
                    for (int b=0;b<4;b++){
                        ulonglong2 h2 = *(const ulonglong2*)(&hbuf[d][b0+b][k]);
                        ffma2(aR[d][b], rA, h2.x); ffma2(aR[d][b], rB, h2.y);
                        ffma2(aZ[d][b], zA, h2.x); ffma2(aZ[d][b], zB, h2.y);
                        ffma2(aN[d][b], nA, h2.x); ffma2(aN[d][b], nB, h2.y);
                    }
                }
            }
            __syncthreads();   // everyone done reading this buffer
            // prefetch chunk (ck+2) mod 8 (wraps into next step's stream)
            int nx = (ck + 2) & 7;
            load_chunk((ck & 1) ? wbuf1 : wbuf0, g_WT2 + (long)nx*W_CHUNK_ULL, tid);
        }

        float hnew[2][4];
        #pragma unroll
        for (int d=0;d<2;d++){
            const float* Gd = d ? GB : GF;
            #pragma unroll
            for (int b=0;b<4;b++){
                float sr = hsum2(aR[d][b]);
                float sz = hsum2(aZ[d][b]);
                float sn = hsum2(aN[d][b]);
                float hold = hbuf[d][b0+b][c];
                float r  = sigmf(__ldg(Gd + (b0+b)*G3        + c) + sr + br);
                float z  = sigmf(__ldg(Gd + (b0+b)*G3 + SS   + c) + sz + bz);
                float ng = tanhfast(__ldg(Gd + (b0+b)*G3 + 2*SS + c) + r*(sn + bn_));
                hnew[d][b] = (1.f - z)*ng + z*hold;
            }
        }
        __syncthreads();                 // all reads of old h done
        #pragma unroll
        for (int d=0;d<2;d++)
            #pragma unroll
            for (int b=0;b<4;b++) hbuf[d][b0+b][c] = hnew[d][b];

        if (i+t < NN){                   // forward: row=i, col=i+t
            int row = i, col = i+t;
            long idx = (long)row*NN - (long)row*(row-1)/2 + (col-row);
            float* dst = out + idx*(BB*TWOH) + c;
            #pragma unroll
            for (int b=0;b<4;b++) dst[(b0+b)*TWOH] = hnew[0][b];
        }
        if (i-t >= 0){                   // backward: row=i-t, col=i
            int row = i-t, col = i;
            long idx = (long)row*NN - (long)row*(row-1)/2 + (col-row);
            float* dst = out + idx*(BB*TWOH) + SS + c;
            #pragma unroll
            for (int b=0;b<4;b++) dst[(b0+b)*TWOH] = hnew[1][b];
        }
        if (i == NN-1){
            if (t == 0){
                float* hd = out + OUT_TRI + c;
                #pragma unroll
                for (int b=0;b<4;b++) hd[(b0+b)*TWOH] = hnew[0][b];
            }
            if (t == TSEG-1){
                float* hd = out + OUT_TRI + SS + c;
                #pragma unroll
                for (int b=0;b<4;b++) hd[(b0+b)*TWOH] = hnew[1][b];
            }
        }
        __syncthreads();                 // new h visible before next step
    }
    // drain outstanding prefetches before exit
    asm volatile("cp.async.wait_group 0;" ::: "memory");
}

// ------------------------------- launcher -----------------------------------
extern "C" void kernel_launch(void* const* d_in, const int* in_sizes, int n_in,
                              void* d_out, int out_size)
{
    const int*   tokens = (const int*)  d_in[0];
    const float* emb    = (const float*)d_in[1];
    const float* Wi_f   = (const float*)d_in[2];
    const float* Wh_f   = (const float*)d_in[3];
    const float* bi_f   = (const float*)d_in[4];
    const float* bh_f   = (const float*)d_in[5];
    const float* Wi_r   = (const float*)d_in[6];
    const float* Wh_r   = (const float*)d_in[7];
    const float* bi_r   = (const float*)d_in[8];
    const float* bh_r   = (const float*)d_in[9];
    const float* Wi_s   = (const float*)d_in[10];
    const float* Wh_s   = (const float*)d_in[11];
    const float* bi_s   = (const float*)d_in[12];
    const float* bh_s   = (const float*)d_in[13];
    const float* h0f    = (const float*)d_in[14];
    const float* h0b    = (const float*)d_in[15];
    float* out = (float*)d_out;

    cudaFuncSetAttribute(k_seg, cudaFuncAttributeMaxDynamicSharedMemorySize, SEG_SMEM);

    k_init_embed<<<4096, 256>>>(out, tokens, emb);      // 1

    dim3 gg(G3/64, (NN*BB)/64);                          // (12, 16)
    k_gemm<<<gg, 256>>>(0, Wi_f, bi_f, EE);              // 2
    k_gemm<<<gg, 256>>>(1, Wi_r, bi_r, EE);              // 3

    k_seqgru<<<128, 256>>>(Wh_f, Wh_r, bh_f, bh_r);      // 4

    dim3 gt(SS/32, G3/32);                               // (8, 24)
    k_transpose<<<gt, 256>>>(Wh_s);                      // 5

    k_gemm<<<gg, 256>>>(2, Wi_s, bi_s, TWOH);            // 6 (profiled slot)

    k_seg<<<128, 512, SEG_SMEM>>>(bh_s, h0f, h0b, out);  // 7
}

// round 16
// speedup vs baseline: 1.5196x; 1.0156x over previous
#include <cuda_runtime.h>
#include <cuda_bf16.h>
#include <cstdint>

// Problem constants
#define NN   128      // sequence length
#define BB   8        // batch
#define EE   256      // embed dim
#define HH   256      // hidden dim (seq GRU)
#define SS   256      // segment dim
#define TSEG 32       // segment window length
#define G3   768      // 3*H == 3*S (gate dim)
#define TWOH 512      // 2*H == 2*S
#define TRI_CNT  8256                  // N*(N+1)/2
#define OUT_TRI  33816576              // TRI_CNT*B*2S
#define OUT_TOTAL 33820672             // + B*2S (hidden)

typedef unsigned long long ull;

#define W_CHUNK_ULL 12288               /* 16 k2-rows x 768 ull = 96 KB */
#define W_CHUNK_BYTES 98304
#define MB_ULL      16                  /* 128B mbarrier region */
#define HB_ULL      2048                /* 16 KB of hbuf in ull units */
#define SEG_SMEM    ((MB_ULL + HB_ULL + 2*W_CHUNK_ULL)*8)   /* 213120 B */

// ------------------------------- scratch -----------------------------------
__device__ float g_x[NN*BB*EE];          // embedded inputs (N*B, E)
__device__ float g_gi_f[NN*BB*G3];       // forward  seq input gates
__device__ float g_gi_r[NN*BB*G3];       // backward seq input gates (step-indexed)
__device__ float g_seqout[NN*BB*TWOH];   // bidirectional GRU outputs (N,B,2H)
__device__ float g_G[NN*BB*G3];          // segment input gates per column j
__device__ float g_h[2*2*BB*HH];         // [parity][dir][b][h] double-buffered seq state
__device__ ull   g_WT2[(SS/2)*G3];       // transposed+paired seg weights:
                                         //   WT2[k2][gate*256+c] = (w[2k2][c], w[2k2+1][c])
__device__ unsigned int g_ctrs[16*32];   // per-(dir,b) barrier counters, 128B apart

__device__ __forceinline__ float sigmf(float x)    { return 1.f/(1.f+__expf(-x)); }
__device__ __forceinline__ float tanhfast(float x) { return 2.f/(1.f+__expf(-2.f*x)) - 1.f; }

// packed fp32x2 FMA (Blackwell FFMA2): d = a*b + d, per 32-bit lane
__device__ __forceinline__ void ffma2(ull &d, ull a, ull b){
    asm("fma.rn.f32x2 %0, %1, %2, %0;" : "+l"(d) : "l"(a), "l"(b));
}
__device__ __forceinline__ float hsum2(ull v){
    float lo, hi;
    asm("mov.b64 {%0,%1}, %2;" : "=f"(lo), "=f"(hi) : "l"(v));
    return lo + hi;
}
__device__ __forceinline__ ull pack2(float lo, float hi){
    ull d;
    asm("mov.b64 %0, {%1,%2};" : "=l"(d) : "f"(lo), "f"(hi));
    return d;
}
__device__ __forceinline__ uint32_t smem_u32(const void* p){
    uint32_t a;
    asm("{ .reg .u64 t; cvta.to.shared.u64 t, %1; cvt.u32.u64 %0, t; }"
        : "=r"(a) : "l"(p));
    return a;
}

// release arrive / acquire poll for the group barriers (no full membar)
__device__ __forceinline__ void bar_arrive(unsigned int* ctr){
    asm volatile("red.release.gpu.global.add.u32 [%0], 1;" :: "l"(ctr) : "memory");
}
__device__ __forceinline__ unsigned int ld_acq(const unsigned int* p){
    unsigned int v;
    asm volatile("ld.acquire.gpu.global.u32 %0, [%1];" : "=r"(v) : "l"(p) : "memory");
    return v;
}

// ---- mbarrier + bulk-copy helpers (single-thread producer) -----------------
__device__ __forceinline__ void mbar_init(uint32_t mbar, uint32_t count){
    asm volatile("mbarrier.init.shared.b64 [%0], %1;" :: "r"(mbar), "r"(count) : "memory");
}
__device__ __forceinline__ void mbar_expect_tx(uint32_t mbar, uint32_t bytes){
    asm volatile("mbarrier.arrive.expect_tx.shared.b64 _, [%0], %1;"
                 :: "r"(mbar), "r"(bytes) : "memory");
}
__device__ __forceinline__ void mbar_wait(uint32_t mbar, uint32_t parity){
    asm volatile(
        "{\n\t.reg .pred P;\n\t"
        "WL%=:\n\t"
        "mbarrier.try_wait.parity.acquire.cta.shared::cta.b64 P, [%0], %1, 0x989680;\n\t"
        "@P bra WD%=;\n\t"
        "bra WL%=;\n\t"
        "WD%=:\n\t}"
        :: "r"(mbar), "r"(parity) : "memory");
}
__device__ __forceinline__ void bulk_copy(uint32_t smem_dst, const void* gsrc,
                                          uint32_t bytes, uint32_t mbar){
    asm volatile(
        "cp.async.bulk.shared::cta.global.mbarrier::complete_tx::bytes [%0], [%1], %2, [%3];"
        :: "r"(smem_dst), "l"(gsrc), "r"(bytes), "r"(mbar) : "memory");
}

// ----------------- init (zero) + embedding + weight transpose ---------------
__global__ void k_init_embed(float* __restrict__ out,
                             const int* __restrict__ tokens,
                             const float* __restrict__ emb,
                             const float* __restrict__ Whs)
{
    __shared__ float tile[32][33];
    long tid    = (long)blockIdx.x*blockDim.x + threadIdx.x;
    long stride = (long)gridDim.x*blockDim.x;
    float4 z = make_float4(0.f,0.f,0.f,0.f);
    float4* o4 = (float4*)out;
    for (long i=tid; i < OUT_TOTAL/4; i+=stride) o4[i] = z;
    if (tid < 2*2*BB*HH) g_h[tid] = 0.f;
    if (tid < 16*32)     g_ctrs[tid] = 0u;
    // embedding: blocks 0..1023 each copy one (n,b) row of 256 floats
    if (blockIdx.x < NN*BB){
        int m = blockIdx.x;
        int tok = tokens[m];
        g_x[(long)m*EE + threadIdx.x] = __ldg(emb + (long)tok*EE + threadIdx.x);
    }
    // transpose+pair segment weights: blocks 1024..1215, one 32x32 tile each.
    // Whs[row][k] (768 x 256) -> g_WT2[k2][row], k-pairs packed in one ull.
    if (blockIdx.x >= NN*BB && blockIdx.x < NN*BB + 192){
        int idx = blockIdx.x - NN*BB;
        int tk = (idx & 7)*32;           // k-block
        int tr = (idx >> 3)*32;          // row-block
        int tx = threadIdx.x & 31, ty = threadIdx.x >> 5;   // 32 x 8
        #pragma unroll
        for (int r=ty; r<32; r+=8)
            tile[r][tx] = __ldg(Whs + (long)(tr+r)*SS + tk + tx);
        __syncthreads();
        #pragma unroll
        for (int k2=ty; k2<16; k2+=8){
            ull v = pack2(tile[tx][2*k2], tile[tx][2*k2+1]);
            g_WT2[(long)((tk>>1)+k2)*G3 + tr + tx] = v;
        }
    }
}

// ------------------------------- NT GEMM ------------------------------------
// C[m][n] = bias[n] + dot(A[m,0:K], W[n,0:K]);  N fixed = 768.
__global__ __launch_bounds__(256) void k_gemm(int mode, const float* __restrict__ W,
                                              const float* __restrict__ bias, int K)
{
    const float* A; float* C; int rev = 0;
    if (mode == 0)      { A = g_x;      C = g_gi_f; }
    else if (mode == 1) { A = g_x;      C = g_gi_r; rev = 1; }
    else                { A = g_seqout; C = g_G;    }

    __shared__ float As[16][68];
    __shared__ float Ws[16][68];
    int bm = blockIdx.y*64, bn = blockIdx.x*64;
    int tid = threadIdx.x;
    int tx = tid & 15, ty = tid >> 4;
    float acc[4][4];
    #pragma unroll
    for (int i=0;i<4;i++)
        #pragma unroll
        for (int j=0;j<4;j++) acc[i][j]=0.f;

    int lr = tid >> 2, lk = (tid & 3) << 2;
    const float* Ap = A + (long)(bm+lr)*K + lk;
    const float* Wp = W + (long)(bn+lr)*K + lk;

    for (int k0=0;k0<K;k0+=16){
        float4 av = *(const float4*)(Ap + k0);
        float4 wv = __ldg((const float4*)(Wp + k0));
        As[lk+0][lr]=av.x; As[lk+1][lr]=av.y; As[lk+2][lr]=av.z; As[lk+3][lr]=av.w;
        Ws[lk+0][lr]=wv.x; Ws[lk+1][lr]=wv.y; Ws[lk+2][lr]=wv.z; Ws[lk+3][lr]=wv.w;
        __syncthreads();
        #pragma unroll
        for (int k=0;k<16;k++){
            float a0=As[k][ty*4+0], a1=As[k][ty*4+1], a2=As[k][ty*4+2], a3=As[k][ty*4+3];
            float b0=Ws[k][tx*4+0], b1=Ws[k][tx*4+1], b2=Ws[k][tx*4+2], b3=Ws[k][tx*4+3];
            acc[0][0]+=a0*b0; acc[0][1]+=a0*b1; acc[0][2]+=a0*b2; acc[0][3]+=a0*b3;
            acc[1][0]+=a1*b0; acc[1][1]+=a1*b1; acc[1][2]+=a1*b2; acc[1][3]+=a1*b3;
            acc[2][0]+=a2*b0; acc[2][1]+=a2*b1; acc[2][2]+=a2*b2; acc[2][3]+=a2*b3;
            acc[3][0]+=a3*b0; acc[3][1]+=a3*b1; acc[3][2]+=a3*b2; acc[3][3]+=a3*b3;
        }
        __syncthreads();
    }
    #pragma unroll
    for (int i=0;i<4;i++){
        int m  = bm + ty*4 + i;
        int mo = m;
        if (rev){ int t = m >> 3, b = m & 7; mo = ((NN-1-t)<<3) | b; }
        #pragma unroll
        for (int j=0;j<4;j++){
            int n = bn + tx*4 + j;
            C[(long)mo*G3 + n] = acc[i][j] + __ldg(bias + n);
        }
    }
}

// -------------------------- bidirectional seq GRU ---------------------------
// (known ~366us) 128 CTAs x 256 thr. Unit=(dir,b,j): 4096 units, 8 threads/
// unit (K split 32). Weights register-resident. Each CTA in one (dir,b) group
// of 8; per-group release/acquire barrier per step.
__global__ __launch_bounds__(256) void k_seqgru(const float* __restrict__ Whf,
                                                const float* __restrict__ Whr,
                                                const float* __restrict__ bhf,
                                                const float* __restrict__ bhr)
{
    int gt  = blockIdx.x*256 + threadIdx.x;
    int q   = gt & 7;
    int u   = gt >> 3;
    int j   = u & 255;
    int b   = (u >> 8) & 7;
    int dir = (u >> 11) & 1;
    const float* Wh = dir ? Whr : Whf;
    const float* bh = dir ? bhr : bhf;
    const float* gi = dir ? g_gi_r : g_gi_f;
    int k0 = q*32;
    unsigned int* ctr = &g_ctrs[(blockIdx.x >> 3)*32];   // group = (dir<<3)|b

    float wr[32], wz[32], wn[32];
    const float* pr = Wh + (long)(0*HH + j)*HH + k0;
    const float* pz = Wh + (long)(1*HH + j)*HH + k0;
    const float* pn = Wh + (long)(2*HH + j)*HH + k0;
    #pragma unroll
    for (int kk=0;kk<32;kk+=4){
        float4 v;
        v = __ldg((const float4*)(pr+kk)); wr[kk]=v.x; wr[kk+1]=v.y; wr[kk+2]=v.z; wr[kk+3]=v.w;
        v = __ldg((const float4*)(pz+kk)); wz[kk]=v.x; wz[kk+1]=v.y; wz[kk+2]=v.z; wz[kk+3]=v.w;
        v = __ldg((const float4*)(pn+kk)); wn[kk]=v.x; wn[kk+1]=v.y; wn[kk+2]=v.z; wn[kk+3]=v.w;
    }
    float br  = __ldg(bh + j);
    float bz  = __ldg(bh + HH + j);
    float bn_ = __ldg(bh + 2*HH + j);

    unsigned int target = 0;
    for (int t=0; t<NN; t++){
        const float* hc = g_h + (((t&1)<<1) | dir)*(BB*HH) + b*HH;
        float sr=0.f, sz=0.f, sn=0.f;
        #pragma unroll
        for (int kk=0;kk<32;kk+=4){
            float4 hv = __ldcg((const float4*)(hc + k0 + kk));
            sr += wr[kk]*hv.x + wr[kk+1]*hv.y + wr[kk+2]*hv.z + wr[kk+3]*hv.w;
            sz += wz[kk]*hv.x + wz[kk+1]*hv.y + wz[kk+2]*hv.z + wz[kk+3]*hv.w;
            sn += wn[kk]*hv.x + wn[kk+1]*hv.y + wn[kk+2]*hv.z + wn[kk+3]*hv.w;
        }
        #pragma unroll
        for (int off=1; off<8; off<<=1){
            sr += __shfl_xor_sync(0xffffffffu, sr, off);
            sz += __shfl_xor_sync(0xffffffffu, sz, off);
            sn += __shfl_xor_sync(0xffffffffu, sn, off);
        }
        const float* gib = gi + (long)((t<<3) + b)*G3;
        float gr = __ldg(gib + j);
        float gz = __ldg(gib + HH + j);
        float gn = __ldg(gib + 2*HH + j);
        float hold = __ldcg(hc + j);

        float r  = sigmf(gr + sr + br);
        float z  = sigmf(gz + sz + bz);
        float ng = tanhfast(gn + r*(sn + bn_));
        float hn = (1.f - z)*ng + z*hold;

        if (q == 0){
            __stcg(g_h + ((((t+1)&1)<<1) | dir)*(BB*HH) + b*HH + j, hn);
            int row = dir ? (NN-1-t) : t;
            g_seqout[(long)((row<<3)+b)*TWOH + (dir<<8) + j] = hn;
        }

        // group barrier (8 co-resident CTAs of this (dir,b) chain)
        target += 8;
        __syncthreads();
        if (threadIdx.x == 0){
            bar_arrive(ctr);
            while (ld_acq(ctr) < target) { }
        }
        __syncthreads();
    }
}

// ----------------------------- segment GRUs ---------------------------------
// 128 CTAs x 512 threads: thread = (c, b-half). Weights staged through smem
// with cp.async.bulk double buffering: ONE thread issues a 96KB bulk copy per
// chunk (no per-thread LDGSTS issue cost), completion via mbarrier; tid0
// parity-waits, everyone else just passes the bar.sync. FFMA2 inner product
// reads weights as coalesced LDS.64 and h as broadcast LDS.128.
__global__ __launch_bounds__(512) void k_seg(const float* __restrict__ bhs,
                                             const float* __restrict__ h0f,
                                             const float* __restrict__ h0b,
                                             float* __restrict__ out)
{
    extern __shared__ __align__(16) ull dsm[];
    uint32_t mb0 = smem_u32(dsm);                       // mbarrier buffer 0
    uint32_t mb1 = mb0 + 8;                             // mbarrier buffer 1
    float (*hbuf)[BB][SS] = (float (*)[BB][SS])(dsm + MB_ULL);   // 16KB
    ull* wbuf0 = dsm + MB_ULL + HB_ULL;                 // 96KB chunk buffer 0
    ull* wbuf1 = dsm + MB_ULL + HB_ULL + W_CHUNK_ULL;   // 96KB chunk buffer 1
    uint32_t wb0s = smem_u32(wbuf0);
    uint32_t wb1s = smem_u32(wbuf1);

    int i   = blockIdx.x;
    int tid = threadIdx.x;
    int c   = tid & 255;
    int bh  = tid >> 8;              // batch half: rows [bh*4, bh*4+4)
    int b0  = bh*4;

    if (tid == 0){
        mbar_init(mb0, 1);
        mbar_init(mb1, 1);
    }
    __syncthreads();
    if (tid == 0){
        mbar_expect_tx(mb0, W_CHUNK_BYTES);
        bulk_copy(wb0s, g_WT2,               W_CHUNK_BYTES, mb0);
        mbar_expect_tx(mb1, W_CHUNK_BYTES);
        bulk_copy(wb1s, g_WT2 + W_CHUNK_ULL, W_CHUNK_BYTES, mb1);
    }

    const float* h0F = h0f + (long)i*BB*SS;
    const float* h0B = h0b + (long)i*BB*SS;
    for (int idx=tid; idx<BB*SS; idx+=512){
        ((float*)hbuf[0])[idx] = h0F[idx];
        ((float*)hbuf[1])[idx] = h0B[idx];
    }

    float br  = __ldg(bhs + c);
    float bz  = __ldg(bhs + SS + c);
    float bn_ = __ldg(bhs + 2*SS + c);
    __syncthreads();

    int ph0 = 0, ph1 = 0;            // phase trackers (used by tid 0)

    for (int t=0; t<TSEG; t++){
        int jF = min(i+t, NN-1);
        int jB = max(i-t, 0);
        const float* GF = g_G + (long)jF*BB*G3;
        const float* GB = g_G + (long)jB*BB*G3;

        ull aR[2][4], aZ[2][4], aN[2][4];
        #pragma unroll
        for (int d=0;d<2;d++)
            #pragma unroll
            for (int b=0;b<4;b++){ aR[d][b]=0ull; aZ[d][b]=0ull; aN[d][b]=0ull; }

        // 8 chunks of 16 k2 (32 k) each; buffer parity = ck & 1
        for (int ck=0; ck<8; ck++){
            int s = ck & 1;
            if (tid == 0){
                if (s == 0){ mbar_wait(mb0, ph0); ph0 ^= 1; }
                else       { mbar_wait(mb1, ph1); ph1 ^= 1; }
            }
            __syncthreads();
            const ull* w = s ? wbuf1 : wbuf0;

            #pragma unroll
            for (int g2=0; g2<8; g2++){
                ull rA = w[(2*g2  )*G3       + c];
                ull rB = w[(2*g2+1)*G3       + c];
                ull zA = w[(2*g2  )*G3 + 256 + c];
                ull zB = w[(2*g2+1)*G3 + 256 + c];
                ull nA = w[(2*g2  )*G3 + 512 + c];
                ull nB = w[(2*g2+1)*G3 + 512 + c];
                int k = ck*32 + g2*4;
                #pragma unroll
                for (int d=0;d<2;d++){
                    #pragma unroll
                    for (int b=0;b<4;b++){
                        ulonglong2 h2 = *(const ulonglong2*)(&hbuf[d][b0+b][k]);
                        ffma2(aR[d][b], rA, h2.x); ffma2(aR[d][b], rB, h2.y);
                        ffma2(aZ[d][b], zA, h2.x); ffma2(aZ[d][b], zB, h2.y);
                        ffma2(aN[d][b], nA, h2.x); ffma2(aN[d][b], nB, h2.y);
                    }
                }
            }
            __syncthreads();   // everyone done reading this buffer
            // prefetch chunk (ck+2) mod 8 (wraps into next step's stream);
            // suppress on the final step so nothing is outstanding at exit.
            bool last = (t == TSEG-1) && (ck >= 6);
            if (tid == 0 && !last){
                int nx = (ck + 2) & 7;
                uint32_t mbs = s ? mb1 : mb0;
                uint32_t dst = s ? wb1s : wb0s;
                mbar_expect_tx(mbs, W_CHUNK_BYTES);
                bulk_copy(dst, g_WT2 + (long)nx*W_CHUNK_ULL, W_CHUNK_BYTES, mbs);
            }
        }

        float hnew[2][4];
        #pragma unroll
        for (int d=0;d<2;d++){
            const float* Gd = d ? GB : GF;
            #pragma unroll
            for (int b=0;b<4;b++){
                float sr = hsum2(aR[d][b]);
                float sz = hsum2(aZ[d][b]);
                float sn = hsum2(aN[d][b]);
                float hold = hbuf[d][b0+b][c];
                float r  = sigmf(__ldg(Gd + (b0+b)*G3        + c) + sr + br);
                float z  = sigmf(__ldg(Gd + (b0+b)*G3 + SS   + c) + sz + bz);
                float ng = tanhfast(__ldg(Gd + (b0+b)*G3 + 2*SS + c) + r*(sn + bn_));
                hnew[d][b] = (1.f - z)*ng + z*hold;
            }
        }
        __syncthreads();                 // all reads of old h done
        #pragma unroll
        for (int d=0;d<2;d++)
            #pragma unroll
            for (int b=0;b<4;b++) hbuf[d][b0+b][c] = hnew[d][b];

        if (i+t < NN){                   // forward: row=i, col=i+t
            int row = i, col = i+t;
            long idx = (long)row*NN - (long)row*(row-1)/2 + (col-row);
            float* dst = out + idx*(BB*TWOH) + c;
            #pragma unroll
            for (int b=0;b<4;b++) dst[(b0+b)*TWOH] = hnew[0][b];
        }
        if (i-t >= 0){                   // backward: row=i-t, col=i
            int row = i-t, col = i;
            long idx = (long)row*NN - (long)row*(row-1)/2 + (col-row);
            float* dst = out + idx*(BB*TWOH) + SS + c;
            #pragma unroll
            for (int b=0;b<4;b++) dst[(b0+b)*TWOH] = hnew[1][b];
        }
        if (i == NN-1){
            if (t == 0){
                float* hd = out + OUT_TRI + c;
                #pragma unroll
                for (int b=0;b<4;b++) hd[(b0+b)*TWOH] = hnew[0][b];
            }
            if (t == TSEG-1){
                float* hd = out + OUT_TRI + SS + c;
                #pragma unroll
                for (int b=0;b<4;b++) hd[(b0+b)*TWOH] = hnew[1][b];
            }
        }
        __syncthreads();                 // new h visible before next step
    }
}

// ------------------------------- launcher -----------------------------------
extern "C" void kernel_launch(void* const* d_in, const int* in_sizes, int n_in,
                              void* d_out, int out_size)
{
    const int*   tokens = (const int*)  d_in[0];
    const float* emb    = (const float*)d_in[1];
    const float* Wi_f   = (const float*)d_in[2];
    const float* Wh_f   = (const float*)d_in[3];
    const float* bi_f   = (const float*)d_in[4];
    const float* bh_f   = (const float*)d_in[5];
    const float* Wi_r   = (const float*)d_in[6];
    const float* Wh_r   = (const float*)d_in[7];
    const float* bi_r   = (const float*)d_in[8];
    const float* bh_r   = (const float*)d_in[9];
    const float* Wi_s   = (const float*)d_in[10];
    const float* Wh_s   = (const float*)d_in[11];
    const float* bi_s   = (const float*)d_in[12];
    const float* bh_s   = (const float*)d_in[13];
    const float* h0f    = (const float*)d_in[14];
    const float* h0b    = (const float*)d_in[15];
    float* out = (float*)d_out;

    cudaFuncSetAttribute(k_seg, cudaFuncAttributeMaxDynamicSharedMemorySize, SEG_SMEM);

    k_init_embed<<<4096, 256>>>(out, tokens, emb, Wh_s); // 1 (zero+embed+transpose)

    dim3 gg(G3/64, (NN*BB)/64);                          // (12, 16)
    k_gemm<<<gg, 256>>>(0, Wi_f, bi_f, EE);              // 2
    k_gemm<<<gg, 256>>>(1, Wi_r, bi_r, EE);              // 3

    k_seqgru<<<128, 256>>>(Wh_f, Wh_r, bh_f, bh_r);      // 4

    k_gemm<<<gg, 256>>>(2, Wi_s, bi_s, TWOH);            // 5

    k_seg<<<128, 512, SEG_SMEM>>>(bh_s, h0f, h0b, out);  // 6 (profiled slot)
}